// round 1
// baseline (speedup 1.0000x reference)
#include <cuda_runtime.h>

// Conv(1->1, 5x5, SAME) + FastLIF + FastLI, fused over the time loop.
// x: [256, 1, 512, 512] f32, kernel: [1,1,5,5] f32, out: [256,1,512,512] f32.
//
// Each CTA owns a 32(W) x 16(H) spatial tile; 128 threads, each thread a
// 2x2 micro-tile, s1/s2 state in registers, loop over t.

#define T_STEPS 256
#define HDIM 512
#define WDIM 512
#define HW (HDIM * WDIM)

#define TILE_W 32
#define TILE_H 16
#define SW 36          // TILE_W + 4 halo
#define SH 20          // TILE_H + 4 halo
#define SSTRIDE 40     // padded row stride (floats)

#define ALPHA_LIF 0.85f
#define V_TH 2.0f
#define ALPHA_LI 0.9f

__global__ __launch_bounds__(128)
void snn_fused_kernel(const float* __restrict__ x,
                      const float* __restrict__ kern,
                      float* __restrict__ out)
{
    __shared__ float smem[SH][SSTRIDE];

    const int tid = threadIdx.x;
    const int tx = tid & 15;   // 0..15 -> 2 output cols each
    const int ty = tid >> 4;   // 0..7  -> 2 output rows each

    const int tileX = blockIdx.x;
    const int tileY = blockIdx.y;
    const int colBase = tileX * TILE_W - 2;   // gmem col of smem col 0
    const int rowBase = tileY * TILE_H - 2;   // gmem row of smem row 0

    // Load 5x5 weights into registers (uniform across threads).
    float w[25];
#pragma unroll
    for (int i = 0; i < 25; i++) w[i] = kern[i];

    const int lr = ty * 2;               // smem window top row for this thread
    const int lc = tx * 2;               // smem window left col
    const int gr0 = tileY * TILE_H + ty * 2;   // gmem out row
    const int gc0 = tileX * TILE_W + tx * 2;   // gmem out col (even -> 8B aligned)

    float s1[4] = {0.f, 0.f, 0.f, 0.f};  // [o_r*2 + o_c]
    float s2[4] = {0.f, 0.f, 0.f, 0.f};

    for (int t = 0; t < T_STEPS; t++) {
        const float* __restrict__ xt = x + (size_t)t * HW;

        // ---- cooperative smem fill: 20 rows x 18 float2 = 360 units ----
        for (int i = tid; i < SH * (SW / 2); i += 128) {
            int r = i / (SW / 2);
            int u = i - r * (SW / 2);
            int gr = rowBase + r;
            int gc = colBase + 2 * u;    // even -> float2 fully in or out of range
            float2 v = make_float2(0.f, 0.f);
            if (gr >= 0 && gr < HDIM && gc >= 0 && gc < WDIM)
                v = *reinterpret_cast<const float2*>(xt + (size_t)gr * WDIM + gc);
            smem[r][2 * u]     = v.x;
            smem[r][2 * u + 1] = v.y;
        }
        __syncthreads();

        // ---- 2x2 conv via row-sliding register window ----
        float acc[4] = {0.f, 0.f, 0.f, 0.f};
#pragma unroll
        for (int r = 0; r < 6; r++) {
            const float2* row = reinterpret_cast<const float2*>(&smem[lr + r][lc]);
            float2 a = row[0];
            float2 b = row[1];
            float2 c = row[2];
            float f[6] = {a.x, a.y, b.x, b.y, c.x, c.y};
#pragma unroll
            for (int o_r = 0; o_r < 2; o_r++) {
                const int kr = r - o_r;
                if (kr >= 0 && kr < 5) {
#pragma unroll
                    for (int kc = 0; kc < 5; kc++) {
                        acc[o_r * 2 + 0] = fmaf(f[kc],     w[kr * 5 + kc], acc[o_r * 2 + 0]);
                        acc[o_r * 2 + 1] = fmaf(f[kc + 1], w[kr * 5 + kc], acc[o_r * 2 + 1]);
                    }
                }
            }
        }

        // ---- LIF + LI recurrence, store s2 ----
        float* __restrict__ ot = out + (size_t)t * HW;
#pragma unroll
        for (int o_r = 0; o_r < 2; o_r++) {
            float2 o2;
#pragma unroll
            for (int o_c = 0; o_c < 2; o_c++) {
                const int k = o_r * 2 + o_c;
                float v = ALPHA_LIF * s1[k] + acc[k];
                float spk = (v >= V_TH) ? 1.0f : 0.0f;
                s1[k] = v - spk * V_TH;
                s2[k] = ALPHA_LI * s2[k] + spk;
                (&o2.x)[o_c] = s2[k];
            }
            *reinterpret_cast<float2*>(ot + (size_t)(gr0 + o_r) * WDIM + gc0) = o2;
        }
        __syncthreads();   // protect smem before next-t refill
    }
}

extern "C" void kernel_launch(void* const* d_in, const int* in_sizes, int n_in,
                              void* d_out, int out_size)
{
    // Inputs per metadata order: x (67108864 f32), kernel (25 f32).
    // Be defensive about ordering: pick by size.
    const float* x = (const float*)d_in[0];
    const float* k = (const float*)d_in[1];
    if (in_sizes[0] == 25) { const float* tmp = x; x = k; k = tmp; }

    float* out = (float*)d_out;

    dim3 grid(WDIM / TILE_W, HDIM / TILE_H);   // 16 x 32 = 512 CTAs
    snn_fused_kernel<<<grid, 128>>>(x, k, out);
}

// round 2
// speedup vs baseline: 2.1048x; 2.1048x over previous
#include <cuda_runtime.h>

// Conv(1->1, 5x5, SAME) + FastLIF + FastLI, fused over the time loop.
// x: [256, 1, 512, 512] f32, kernel: [1,1,5,5] f32, out: [256,1,512,512] f32.
//
// Tile 32(W) x 8(H) per CTA, 128 threads, 2x1 micro-tile per thread.
// 1024 CTAs -> ~7 CTAs/SM (43% occ, balanced waves).
// Gmem->register prefetch of timestep t+1 overlaps compute of t.

#define T_STEPS 256
#define HDIM 512
#define WDIM 512
#define HW (HDIM * WDIM)

#define TILE_W 32
#define TILE_H 8
#define SW 36          // TILE_W + 4 halo
#define SH 12          // TILE_H + 4 halo
#define SSTRIDE 40     // padded row stride (floats)
#define FILL_UNITS (SH * (SW / 2))   // 216 float2 units
#define NPRE 2                        // ceil(216 / 128)

#define ALPHA_LIF 0.85f
#define V_TH 2.0f
#define ALPHA_LI 0.9f

__global__ __launch_bounds__(128)
void snn_fused_kernel(const float* __restrict__ x,
                      const float* __restrict__ kern,
                      float* __restrict__ out)
{
    __shared__ float smem[SH][SSTRIDE];

    const int tid = threadIdx.x;
    const int tx = tid & 15;   // 0..15 -> 2 output cols each
    const int ty = tid >> 4;   // 0..7  -> 1 output row each

    const int tileX = blockIdx.x;
    const int tileY = blockIdx.y;
    const int colBase = tileX * TILE_W - 2;   // gmem col of smem col 0
    const int rowBase = tileY * TILE_H - 2;   // gmem row of smem row 0

    // 5x5 weights in registers (uniform).
    float w[25];
#pragma unroll
    for (int i = 0; i < 25; i++) w[i] = kern[i];

    // ---- precompute fill-slot geometry (time-invariant) ----
    int   fill_smem_r[NPRE], fill_smem_u[NPRE];
    long  fill_gofs[NPRE];
    bool  fill_live[NPRE], fill_valid[NPRE];
#pragma unroll
    for (int j = 0; j < NPRE; j++) {
        int idx = tid + 128 * j;
        fill_live[j] = (idx < FILL_UNITS);
        int r = idx / (SW / 2);
        int u = idx - r * (SW / 2);
        if (!fill_live[j]) { r = 0; u = 0; }
        fill_smem_r[j] = r;
        fill_smem_u[j] = u;
        int gr = rowBase + r;
        int gc = colBase + 2 * u;   // even -> float2 fully in or out of row
        fill_valid[j] = fill_live[j] && (gr >= 0) && (gr < HDIM) && (gc >= 0) && (gc < WDIM);
        fill_gofs[j] = (long)gr * WDIM + gc;
    }

    const int lc  = 2 * tx;                   // smem window left col
    const int gr0 = tileY * TILE_H + ty;      // gmem out row
    const int gc0 = tileX * TILE_W + 2 * tx;  // gmem out col (8B aligned)
    const long out_ofs = (long)gr0 * WDIM + gc0;

    float s1a = 0.f, s1b = 0.f;   // LIF membrane
    float s2a = 0.f, s2b = 0.f;   // LI readout

    // ---- prefetch t = 0 ----
    float2 pre[NPRE];
#pragma unroll
    for (int j = 0; j < NPRE; j++) {
        pre[j] = make_float2(0.f, 0.f);
        if (fill_valid[j])
            pre[j] = *reinterpret_cast<const float2*>(x + fill_gofs[j]);
    }

    for (int t = 0; t < T_STEPS; t++) {
        // ---- commit prefetched tile to smem ----
#pragma unroll
        for (int j = 0; j < NPRE; j++) {
            if (fill_live[j])
                *reinterpret_cast<float2*>(&smem[fill_smem_r[j]][2 * fill_smem_u[j]]) = pre[j];
        }
        __syncthreads();

        // ---- issue prefetch for t+1 (overlaps compute below) ----
        if (t + 1 < T_STEPS) {
            const float* __restrict__ xn = x + (size_t)(t + 1) * HW;
#pragma unroll
            for (int j = 0; j < NPRE; j++) {
                pre[j] = make_float2(0.f, 0.f);
                if (fill_valid[j])
                    pre[j] = *reinterpret_cast<const float2*>(xn + fill_gofs[j]);
            }
        }

        // ---- 2-wide conv from smem ----
        float acc0 = 0.f, acc1 = 0.f;
#pragma unroll
        for (int kr = 0; kr < 5; kr++) {
            const float2* row = reinterpret_cast<const float2*>(&smem[ty + kr][lc]);
            float2 a = row[0];
            float2 b = row[1];
            float2 c = row[2];
            float f[6] = {a.x, a.y, b.x, b.y, c.x, c.y};
#pragma unroll
            for (int kc = 0; kc < 5; kc++) {
                acc0 = fmaf(f[kc],     w[kr * 5 + kc], acc0);
                acc1 = fmaf(f[kc + 1], w[kr * 5 + kc], acc1);
            }
        }

        // ---- LIF + LI recurrence, store s2 ----
        float v0 = ALPHA_LIF * s1a + acc0;
        float v1 = ALPHA_LIF * s1b + acc1;
        float k0 = (v0 >= V_TH) ? 1.0f : 0.0f;
        float k1 = (v1 >= V_TH) ? 1.0f : 0.0f;
        s1a = v0 - k0 * V_TH;
        s1b = v1 - k1 * V_TH;
        s2a = ALPHA_LI * s2a + k0;
        s2b = ALPHA_LI * s2b + k1;

        *reinterpret_cast<float2*>(out + (size_t)t * HW + out_ofs) = make_float2(s2a, s2b);

        __syncthreads();   // smem consumed; safe to refill next iteration
    }
}

extern "C" void kernel_launch(void* const* d_in, const int* in_sizes, int n_in,
                              void* d_out, int out_size)
{
    const float* x = (const float*)d_in[0];
    const float* k = (const float*)d_in[1];
    if (in_sizes[0] == 25) { const float* tmp = x; x = k; k = tmp; }

    float* out = (float*)d_out;

    dim3 grid(WDIM / TILE_W, HDIM / TILE_H);   // 16 x 64 = 1024 CTAs
    snn_fused_kernel<<<grid, 128>>>(x, k, out);
}